// round 14
// baseline (speedup 1.0000x reference)
#include <cuda_runtime.h>
#include <stdint.h>
#include <math.h>

// Problem constants
#define N_SEQ   2048
#define S_SITES 4096
#define WPS4    64           // uint4 (lo,hi)-pairs per sequence (64 x 64 tokens)
#define TILES   136          // 16*17/2 triangle tiles of 128x128
#define STR4    5            // smem row stride in uint4 (4 data + 1 pad)
#define NCHUNK  16           // 16 chunks x 4 uint4/row each

// Scratch (static device globals: allocation-free rule)
__device__ uint2    g_ab[N_SEQ * WPS4 * 2]; // interleaved bit planes (lo, hi)
__device__ float4   g_zs[N_SEQ];            // {z.x, z.y, ||z||^2, 1/(1-||z||^2)}
__device__ float    g_scale;                // exp(log_scale)
__device__ float    g_partial[TILES];       // per-tile weighted partial sums
__device__ unsigned g_count;                // zero-init; self-restoring ticket

// ---------------------------------------------------------------------------
// Kernel 1: pack one-hot fp32 -> bit planes (ballot-based, coalesced) and,
// in blocks 0..7, also normalize the embedding table (fused prep).
// One thread = one site (16B). one-hot 1.0f = 0x3F800000, so bit 29 of the
// OR of the relevant lanes IS the token bit — no float compares needed.
// ---------------------------------------------------------------------------
__global__ void pack_prep_kernel(const float* __restrict__ data,
                                 const float* __restrict__ table,
                                 const float* __restrict__ log_scale) {
    unsigned site = blockIdx.x * 256u + threadIdx.x;   // 0 .. N*S-1
    uint4 u = reinterpret_cast<const uint4*>(data)[site];
    unsigned lo = __ballot_sync(0xffffffffu, (int)((u.y | u.w) & 0x20000000u));
    unsigned hi = __ballot_sync(0xffffffffu, (int)((u.z | u.w) & 0x20000000u));
    if ((threadIdx.x & 31u) == 0u)
        g_ab[site >> 5] = make_uint2(lo, hi);

    // fused prep: 8 blocks x 256 threads = 2048 rows
    if (blockIdx.x < 8) {
        int i = blockIdx.x * 256 + threadIdx.x;
        float x = table[2 * i], y = table[2 * i + 1];
        float norm = sqrtf(x * x + y * y);
        float nm = fmaxf(norm, 1e-12f);
        float f = tanhf(norm) / nm;
        float zx = x * f, zy = y * f;
        float s = zx * zx + zy * zy;
        g_zs[i] = make_float4(zx, zy, s, 1.0f / (1.0f - s));
        if (i == 0) g_scale = expf(log_scale[0]);
    }
}

// ---------------------------------------------------------------------------
// Kernel 2: main. One CTA (1024 threads, 8 warps/SMSP) per 128x128 triangle
// tile (bj <= bi). Thread tile 4(i) x 4(j): warp w owns rows 4w..4w+3 (a-loads
// are warp-broadcast LDS.128 = conflict-free), lane strides j (stride-5 uint4
// rows, conflict-free). Double-buffered smem, register-prefetched LDG, one
// __syncthreads per chunk. Fused hyperbolic epilogue + ticketed final reduce.
// ---------------------------------------------------------------------------
__global__ void __launch_bounds__(1024, 1) ham_kernel(float* __restrict__ out) {
    __shared__ uint4 As4[2][128 * STR4];
    __shared__ uint4 Bs4[2][128 * STR4];
    __shared__ float wsum[32];
    __shared__ int   s_last;

    int k = blockIdx.x;
    int bi = 0;
    while ((bi + 1) * (bi + 2) / 2 <= k) bi++;
    int bj = k - bi * (bi + 1) / 2;

    int tid = threadIdx.x;
    int lane = tid & 31;        // j fine index
    int w    = tid >> 5;        // warp: i group (0..31), rows 4w..4w+3

    // cooperative-load assignment: tid<512 -> A, else B; 1 uint4 per chunk
    int half = tid >> 9;                 // 0 = A, 1 = B
    int lrow = (tid >> 2) & 127;
    int lc4  = tid & 3;

    int acc[4][4];
#pragma unroll
    for (int p = 0; p < 4; p++)
#pragma unroll
        for (int q = 0; q < 4; q++) acc[p][q] = 0;

    const uint4* gsrc = reinterpret_cast<const uint4*>(g_ab)
        + (size_t)((half ? bj : bi) * 128 + lrow) * WPS4 + lc4;
    uint4* sdst0 = (half ? Bs4[0] : As4[0]) + lrow * STR4 + lc4;
    uint4* sdst1 = (half ? Bs4[1] : As4[1]) + lrow * STR4 + lc4;

    // prologue: chunk 0 into buffer 0
    uint4 v = gsrc[0];
    *sdst0 = v;
    __syncthreads();

    for (int c = 0; c < NCHUNK; c++) {
        int cur = c & 1;
        if (c < NCHUNK - 1)
            v = gsrc[(c + 1) * 4];       // prefetch overlaps compute

        const uint4* A = As4[cur];
        const uint4* B = Bs4[cur];
#pragma unroll
        for (int kp = 0; kp < 4; kp++) {
            uint4 a[4], b[4];
#pragma unroll
            for (int p = 0; p < 4; p++)
                a[p] = A[(w * 4 + p) * STR4 + kp];      // warp-broadcast
#pragma unroll
            for (int q = 0; q < 4; q++)
                b[q] = B[(q * 32 + lane) * STR4 + kp];
#pragma unroll
            for (int p = 0; p < 4; p++)
#pragma unroll
                for (int q = 0; q < 4; q++) {
                    // token differs iff low OR high plane bit differs
                    unsigned m0 = (a[p].x ^ b[q].x) | (a[p].y ^ b[q].y);
                    unsigned m1 = (a[p].z ^ b[q].z) | (a[p].w ^ b[q].w);
                    acc[p][q] += __popc(m0) + __popc(m1);   // IADD3
                }
        }

        if (c < NCHUNK - 1) {
            if (cur) *sdst0 = v; else *sdst1 = v;
            __syncthreads();
        }
    }

    // ---------------- fused epilogue ----------------
    float scale = g_scale;
    float4 zi[4], zj[4];
#pragma unroll
    for (int p = 0; p < 4; p++) zi[p] = g_zs[bi * 128 + w * 4 + p];
#pragma unroll
    for (int q = 0; q < 4; q++) zj[q] = g_zs[bj * 128 + q * 32 + lane];

    const float inv_s = 1.0f / 4096.0f;
    float sum = 0.0f;
#pragma unroll
    for (int p = 0; p < 4; p++)
#pragma unroll
        for (int q = 0; q < 4; q++) {
            float ham = (float)acc[p][q] * inv_s;          // exact
            float dx = zi[p].x - zj[q].x;
            float dy = zi[p].y - zj[q].y;
            float dsq = dx * dx + dy * dy;
            float arg = fmaf(2.0f * dsq, zi[p].w * zj[q].w, 1.0f);
            arg = fmaxf(arg, 1.0f + 1e-7f);
            float dist = acoshf(arg) * scale;
            float d = ham - dist;
            sum = fmaf(d, d, sum);
        }

    // tile reduction (32 warps)
#pragma unroll
    for (int o = 16; o > 0; o >>= 1)
        sum += __shfl_down_sync(0xffffffffu, sum, o);
    if (lane == 0) wsum[w] = sum;
    __syncthreads();
    if (tid < 32) {
        float t = wsum[lane];
#pragma unroll
        for (int o = 16; o > 0; o >>= 1)
            t += __shfl_down_sync(0xffffffffu, t, o);
        if (lane == 0) {
            g_partial[k] = t * ((bi == bj) ? 1.0f : 2.0f);
            __threadfence();
            unsigned tk = atomicAdd(&g_count, 1u);
            s_last = (tk == TILES - 1);
        }
    }
    __syncthreads();

    // last CTA: deterministic final reduce (fixed order every replay)
    if (s_last) {
        float vv = (tid < TILES) ? g_partial[tid] : 0.0f;
#pragma unroll
        for (int o = 16; o > 0; o >>= 1)
            vv += __shfl_down_sync(0xffffffffu, vv, o);
        __syncthreads();                 // wsum reuse
        if (lane == 0) wsum[w] = vv;
        __syncthreads();
        if (tid < 32) {
            float t = wsum[lane];
#pragma unroll
            for (int o = 16; o > 0; o >>= 1)
                t += __shfl_down_sync(0xffffffffu, t, o);
            if (lane == 0) {
                out[0] = t * (1.0f / 4194304.0f);   // / 2048^2 (exact pow2)
                g_count = 0u;                        // self-restore for replay
            }
        }
    }
}

// ---------------------------------------------------------------------------
extern "C" void kernel_launch(void* const* d_in, const int* in_sizes, int n_in,
                              void* d_out, int out_size) {
    const float* data   = (const float*)d_in[0];   // [2048,4096,4] fp32 one-hot
    const float* table  = (const float*)d_in[1];   // [2048,2] fp32
    const float* lscale = (const float*)d_in[2];   // scalar fp32

    (void)in_sizes; (void)n_in; (void)out_size;

    pack_prep_kernel<<<(N_SEQ * S_SITES) / 256, 256>>>(data, table, lscale);
    ham_kernel      <<<TILES, 1024>>>((float*)d_out);
}

// round 15
// speedup vs baseline: 1.0003x; 1.0003x over previous
#include <cuda_runtime.h>
#include <stdint.h>
#include <math.h>

// Problem constants
#define N_SEQ   2048
#define S_SITES 4096
#define WPS4    64           // uint4 (lo,hi)-pairs per sequence (64 x 64 tokens)
#define TILES   136          // 16*17/2 triangle tiles of 128x128
#define STR4    5            // smem row stride in uint4 (4 data + 1 pad)
#define NCHUNK  16           // 16 chunks x 4 uint4/row each

// Scratch (static device globals: allocation-free rule)
__device__ uint2    g_ab[N_SEQ * WPS4 * 2]; // interleaved bit planes (lo, hi)
__device__ float4   g_zs[N_SEQ];            // {z.x, z.y, ||z||^2, 1/(1-||z||^2)}
__device__ float    g_scale;                // exp(log_scale)
__device__ float    g_partial[TILES];       // per-tile weighted partial sums
__device__ unsigned g_count;                // zero-init; self-restoring ticket

// ---------------------------------------------------------------------------
// Kernel 1: pack one-hot fp32 -> bit planes (ballot-based, coalesced) and,
// in blocks 0..7, also normalize the embedding table (fused prep).
// One thread = one site (16B). one-hot 1.0f = 0x3F800000, so bit 29 of the
// OR of the relevant lanes IS the token bit — no float compares needed.
// ---------------------------------------------------------------------------
__global__ void pack_prep_kernel(const float* __restrict__ data,
                                 const float* __restrict__ table,
                                 const float* __restrict__ log_scale) {
    unsigned site = blockIdx.x * 256u + threadIdx.x;   // 0 .. N*S-1
    uint4 u = reinterpret_cast<const uint4*>(data)[site];
    unsigned lo = __ballot_sync(0xffffffffu, (int)((u.y | u.w) & 0x20000000u));
    unsigned hi = __ballot_sync(0xffffffffu, (int)((u.z | u.w) & 0x20000000u));
    if ((threadIdx.x & 31u) == 0u)
        g_ab[site >> 5] = make_uint2(lo, hi);

    // fused prep: 8 blocks x 256 threads = 2048 rows
    if (blockIdx.x < 8) {
        int i = blockIdx.x * 256 + threadIdx.x;
        float x = table[2 * i], y = table[2 * i + 1];
        float norm = sqrtf(x * x + y * y);
        float nm = fmaxf(norm, 1e-12f);
        float f = tanhf(norm) / nm;
        float zx = x * f, zy = y * f;
        float s = zx * zx + zy * zy;
        g_zs[i] = make_float4(zx, zy, s, 1.0f / (1.0f - s));
        if (i == 0) g_scale = expf(log_scale[0]);
    }
}

// ---------------------------------------------------------------------------
// Kernel 2: main. One CTA (1024 threads, 8 warps/SMSP) per 128x128 triangle
// tile (bj <= bi). Thread tile 4(i) x 4(j): warp w owns rows 4w..4w+3 (a-loads
// are warp-broadcast LDS.128 = conflict-free), lane strides j (stride-5 uint4
// rows, conflict-free). Double-buffered smem, register-prefetched LDG, one
// __syncthreads per chunk. Fused hyperbolic epilogue + ticketed final reduce.
// ---------------------------------------------------------------------------
__global__ void __launch_bounds__(1024, 1) ham_kernel(float* __restrict__ out) {
    __shared__ uint4 As4[2][128 * STR4];
    __shared__ uint4 Bs4[2][128 * STR4];
    __shared__ float wsum[32];
    __shared__ int   s_last;

    int k = blockIdx.x;
    int bi = 0;
    while ((bi + 1) * (bi + 2) / 2 <= k) bi++;
    int bj = k - bi * (bi + 1) / 2;

    int tid = threadIdx.x;
    int lane = tid & 31;        // j fine index
    int w    = tid >> 5;        // warp: i group (0..31), rows 4w..4w+3

    // cooperative-load assignment: tid<512 -> A, else B; 1 uint4 per chunk
    int half = tid >> 9;                 // 0 = A, 1 = B
    int lrow = (tid >> 2) & 127;
    int lc4  = tid & 3;

    int acc[4][4];
#pragma unroll
    for (int p = 0; p < 4; p++)
#pragma unroll
        for (int q = 0; q < 4; q++) acc[p][q] = 0;

    const uint4* gsrc = reinterpret_cast<const uint4*>(g_ab)
        + (size_t)((half ? bj : bi) * 128 + lrow) * WPS4 + lc4;
    uint4* sdst0 = (half ? Bs4[0] : As4[0]) + lrow * STR4 + lc4;
    uint4* sdst1 = (half ? Bs4[1] : As4[1]) + lrow * STR4 + lc4;

    // prologue: chunk 0 into buffer 0
    uint4 v = gsrc[0];
    *sdst0 = v;
    __syncthreads();

    for (int c = 0; c < NCHUNK; c++) {
        int cur = c & 1;
        if (c < NCHUNK - 1)
            v = gsrc[(c + 1) * 4];       // prefetch overlaps compute

        const uint4* A = As4[cur];
        const uint4* B = Bs4[cur];
#pragma unroll
        for (int kp = 0; kp < 4; kp++) {
            uint4 a[4], b[4];
#pragma unroll
            for (int p = 0; p < 4; p++)
                a[p] = A[(w * 4 + p) * STR4 + kp];      // warp-broadcast
#pragma unroll
            for (int q = 0; q < 4; q++)
                b[q] = B[(q * 32 + lane) * STR4 + kp];
#pragma unroll
            for (int p = 0; p < 4; p++)
#pragma unroll
                for (int q = 0; q < 4; q++) {
                    // token differs iff low OR high plane bit differs
                    unsigned m0 = (a[p].x ^ b[q].x) | (a[p].y ^ b[q].y);
                    unsigned m1 = (a[p].z ^ b[q].z) | (a[p].w ^ b[q].w);
                    acc[p][q] += __popc(m0) + __popc(m1);   // IADD3
                }
        }

        if (c < NCHUNK - 1) {
            if (cur) *sdst0 = v; else *sdst1 = v;
            __syncthreads();
        }
    }

    // ---------------- fused epilogue ----------------
    float scale = g_scale;
    float4 zi[4], zj[4];
#pragma unroll
    for (int p = 0; p < 4; p++) zi[p] = g_zs[bi * 128 + w * 4 + p];
#pragma unroll
    for (int q = 0; q < 4; q++) zj[q] = g_zs[bj * 128 + q * 32 + lane];

    const float inv_s = 1.0f / 4096.0f;
    float sum = 0.0f;
#pragma unroll
    for (int p = 0; p < 4; p++)
#pragma unroll
        for (int q = 0; q < 4; q++) {
            float ham = (float)acc[p][q] * inv_s;          // exact
            float dx = zi[p].x - zj[q].x;
            float dy = zi[p].y - zj[q].y;
            float dsq = dx * dx + dy * dy;
            float arg = fmaf(2.0f * dsq, zi[p].w * zj[q].w, 1.0f);
            arg = fmaxf(arg, 1.0f + 1e-7f);
            float dist = acoshf(arg) * scale;
            float d = ham - dist;
            sum = fmaf(d, d, sum);
        }

    // tile reduction (32 warps)
#pragma unroll
    for (int o = 16; o > 0; o >>= 1)
        sum += __shfl_down_sync(0xffffffffu, sum, o);
    if (lane == 0) wsum[w] = sum;
    __syncthreads();
    if (tid < 32) {
        float t = wsum[lane];
#pragma unroll
        for (int o = 16; o > 0; o >>= 1)
            t += __shfl_down_sync(0xffffffffu, t, o);
        if (lane == 0) {
            g_partial[k] = t * ((bi == bj) ? 1.0f : 2.0f);
            __threadfence();
            unsigned tk = atomicAdd(&g_count, 1u);
            s_last = (tk == TILES - 1);
        }
    }
    __syncthreads();

    // last CTA: deterministic final reduce (fixed order every replay)
    if (s_last) {
        float vv = (tid < TILES) ? g_partial[tid] : 0.0f;
#pragma unroll
        for (int o = 16; o > 0; o >>= 1)
            vv += __shfl_down_sync(0xffffffffu, vv, o);
        __syncthreads();                 // wsum reuse
        if (lane == 0) wsum[w] = vv;
        __syncthreads();
        if (tid < 32) {
            float t = wsum[lane];
#pragma unroll
            for (int o = 16; o > 0; o >>= 1)
                t += __shfl_down_sync(0xffffffffu, t, o);
            if (lane == 0) {
                out[0] = t * (1.0f / 4194304.0f);   // / 2048^2 (exact pow2)
                g_count = 0u;                        // self-restore for replay
            }
        }
    }
}

// ---------------------------------------------------------------------------
extern "C" void kernel_launch(void* const* d_in, const int* in_sizes, int n_in,
                              void* d_out, int out_size) {
    const float* data   = (const float*)d_in[0];   // [2048,4096,4] fp32 one-hot
    const float* table  = (const float*)d_in[1];   // [2048,2] fp32
    const float* lscale = (const float*)d_in[2];   // scalar fp32

    (void)in_sizes; (void)n_in; (void)out_size;

    pack_prep_kernel<<<(N_SEQ * S_SITES) / 256, 256>>>(data, table, lscale);
    ham_kernel      <<<TILES, 1024>>>((float*)d_out);
}

// round 16
// speedup vs baseline: 1.0046x; 1.0043x over previous
#include <cuda_runtime.h>
#include <stdint.h>
#include <math.h>

// Problem constants
#define N_SEQ   2048
#define S_SITES 4096
#define WPS4    64           // uint4 (lo,hi)-pairs per sequence (64 x 64 tokens)
#define TILES   136          // 16*17/2 triangle tiles of 128x128
#define STR4    5            // smem row stride in uint4 (4 data + 1 pad)
#define NCHUNK  16           // 16 chunks x 4 uint4/row each

// Scratch (static device globals: allocation-free rule)
__device__ uint2    g_ab[N_SEQ * WPS4 * 2]; // interleaved bit planes (lo, hi)
__device__ float4   g_zs[N_SEQ];            // {z.x, z.y, ||z||^2, 1/(1-||z||^2)}
__device__ float    g_scale;                // exp(log_scale)
__device__ float    g_partial[TILES];       // per-tile weighted partial sums
__device__ unsigned g_count;                // zero-init; self-restoring ticket

// ---------------------------------------------------------------------------
// Kernel 1: pack one-hot fp32 -> bit planes (ballot-based, coalesced) and,
// in blocks 0..7, also normalize the embedding table (fused prep).
// One thread = one site (16B). one-hot 1.0f = 0x3F800000, so bit 29 of the
// OR of the relevant lanes IS the token bit — no float compares needed.
// ---------------------------------------------------------------------------
__global__ void pack_prep_kernel(const float* __restrict__ data,
                                 const float* __restrict__ table,
                                 const float* __restrict__ log_scale) {
    unsigned site = blockIdx.x * 256u + threadIdx.x;   // 0 .. N*S-1
    uint4 u = reinterpret_cast<const uint4*>(data)[site];
    unsigned lo = __ballot_sync(0xffffffffu, (int)((u.y | u.w) & 0x20000000u));
    unsigned hi = __ballot_sync(0xffffffffu, (int)((u.z | u.w) & 0x20000000u));
    if ((threadIdx.x & 31u) == 0u)
        g_ab[site >> 5] = make_uint2(lo, hi);

    // fused prep: 8 blocks x 256 threads = 2048 rows
    if (blockIdx.x < 8) {
        int i = blockIdx.x * 256 + threadIdx.x;
        float x = table[2 * i], y = table[2 * i + 1];
        float norm = sqrtf(x * x + y * y);
        float nm = fmaxf(norm, 1e-12f);
        float f = tanhf(norm) / nm;
        float zx = x * f, zy = y * f;
        float s = zx * zx + zy * zy;
        g_zs[i] = make_float4(zx, zy, s, 1.0f / (1.0f - s));
        if (i == 0) g_scale = expf(log_scale[0]);
    }
}

// ---------------------------------------------------------------------------
// Kernel 2: main. One CTA (1024 threads, 8 warps/SMSP) per 128x128 triangle
// tile (bj <= bi). Thread tile 4(i) x 4(j): warp w owns rows 4w..4w+3 (a-loads
// are warp-broadcast LDS.128 = conflict-free), lane strides j (stride-5 uint4
// rows, conflict-free). Double-buffered smem, register-prefetched LDG, one
// __syncthreads per chunk. Fused hyperbolic epilogue + ticketed final reduce.
// ---------------------------------------------------------------------------
__global__ void __launch_bounds__(1024, 1) ham_kernel(float* __restrict__ out) {
    __shared__ uint4 As4[2][128 * STR4];
    __shared__ uint4 Bs4[2][128 * STR4];
    __shared__ float wsum[32];
    __shared__ int   s_last;

    int k = blockIdx.x;
    int bi = 0;
    while ((bi + 1) * (bi + 2) / 2 <= k) bi++;
    int bj = k - bi * (bi + 1) / 2;

    int tid = threadIdx.x;
    int lane = tid & 31;        // j fine index
    int w    = tid >> 5;        // warp: i group (0..31), rows 4w..4w+3

    // cooperative-load assignment: tid<512 -> A, else B; 1 uint4 per chunk
    int half = tid >> 9;                 // 0 = A, 1 = B
    int lrow = (tid >> 2) & 127;
    int lc4  = tid & 3;

    int acc[4][4];
#pragma unroll
    for (int p = 0; p < 4; p++)
#pragma unroll
        for (int q = 0; q < 4; q++) acc[p][q] = 0;

    const uint4* gsrc = reinterpret_cast<const uint4*>(g_ab)
        + (size_t)((half ? bj : bi) * 128 + lrow) * WPS4 + lc4;
    uint4* sdst0 = (half ? Bs4[0] : As4[0]) + lrow * STR4 + lc4;
    uint4* sdst1 = (half ? Bs4[1] : As4[1]) + lrow * STR4 + lc4;

    // prologue: chunk 0 into buffer 0
    uint4 v = gsrc[0];
    *sdst0 = v;
    __syncthreads();

    for (int c = 0; c < NCHUNK; c++) {
        int cur = c & 1;
        if (c < NCHUNK - 1)
            v = gsrc[(c + 1) * 4];       // prefetch overlaps compute

        const uint4* A = As4[cur];
        const uint4* B = Bs4[cur];
#pragma unroll
        for (int kp = 0; kp < 4; kp++) {
            uint4 a[4], b[4];
#pragma unroll
            for (int p = 0; p < 4; p++)
                a[p] = A[(w * 4 + p) * STR4 + kp];      // warp-broadcast
#pragma unroll
            for (int q = 0; q < 4; q++)
                b[q] = B[(q * 32 + lane) * STR4 + kp];
#pragma unroll
            for (int p = 0; p < 4; p++)
#pragma unroll
                for (int q = 0; q < 4; q++) {
                    // token differs iff low OR high plane bit differs
                    unsigned m0 = (a[p].x ^ b[q].x) | (a[p].y ^ b[q].y);
                    unsigned m1 = (a[p].z ^ b[q].z) | (a[p].w ^ b[q].w);
                    acc[p][q] += __popc(m0) + __popc(m1);   // IADD3
                }
        }

        if (c < NCHUNK - 1) {
            if (cur) *sdst0 = v; else *sdst1 = v;
            __syncthreads();
        }
    }

    // ---------------- fused epilogue ----------------
    float scale = g_scale;
    float4 zi[4], zj[4];
#pragma unroll
    for (int p = 0; p < 4; p++) zi[p] = g_zs[bi * 128 + w * 4 + p];
#pragma unroll
    for (int q = 0; q < 4; q++) zj[q] = g_zs[bj * 128 + q * 32 + lane];

    const float inv_s = 1.0f / 4096.0f;
    float sum = 0.0f;
#pragma unroll
    for (int p = 0; p < 4; p++)
#pragma unroll
        for (int q = 0; q < 4; q++) {
            float ham = (float)acc[p][q] * inv_s;          // exact
            float dx = zi[p].x - zj[q].x;
            float dy = zi[p].y - zj[q].y;
            float dsq = dx * dx + dy * dy;
            float arg = fmaf(2.0f * dsq, zi[p].w * zj[q].w, 1.0f);
            arg = fmaxf(arg, 1.0f + 1e-7f);
            float dist = acoshf(arg) * scale;
            float d = ham - dist;
            sum = fmaf(d, d, sum);
        }

    // tile reduction (32 warps)
#pragma unroll
    for (int o = 16; o > 0; o >>= 1)
        sum += __shfl_down_sync(0xffffffffu, sum, o);
    if (lane == 0) wsum[w] = sum;
    __syncthreads();
    if (tid < 32) {
        float t = wsum[lane];
#pragma unroll
        for (int o = 16; o > 0; o >>= 1)
            t += __shfl_down_sync(0xffffffffu, t, o);
        if (lane == 0) {
            g_partial[k] = t * ((bi == bj) ? 1.0f : 2.0f);
            __threadfence();
            unsigned tk = atomicAdd(&g_count, 1u);
            s_last = (tk == TILES - 1);
        }
    }
    __syncthreads();

    // last CTA: deterministic final reduce (fixed order every replay)
    if (s_last) {
        float vv = (tid < TILES) ? g_partial[tid] : 0.0f;
#pragma unroll
        for (int o = 16; o > 0; o >>= 1)
            vv += __shfl_down_sync(0xffffffffu, vv, o);
        __syncthreads();                 // wsum reuse
        if (lane == 0) wsum[w] = vv;
        __syncthreads();
        if (tid < 32) {
            float t = wsum[lane];
#pragma unroll
            for (int o = 16; o > 0; o >>= 1)
                t += __shfl_down_sync(0xffffffffu, t, o);
            if (lane == 0) {
                out[0] = t * (1.0f / 4194304.0f);   // / 2048^2 (exact pow2)
                g_count = 0u;                        // self-restore for replay
            }
        }
    }
}

// ---------------------------------------------------------------------------
extern "C" void kernel_launch(void* const* d_in, const int* in_sizes, int n_in,
                              void* d_out, int out_size) {
    const float* data   = (const float*)d_in[0];   // [2048,4096,4] fp32 one-hot
    const float* table  = (const float*)d_in[1];   // [2048,2] fp32
    const float* lscale = (const float*)d_in[2];   // scalar fp32

    (void)in_sizes; (void)n_in; (void)out_size;

    pack_prep_kernel<<<(N_SEQ * S_SITES) / 256, 256>>>(data, table, lscale);
    ham_kernel      <<<TILES, 1024>>>((float*)d_out);
}